// round 1
// baseline (speedup 1.0000x reference)
#include <cuda_runtime.h>
#include <math.h>

// Problem constants (fixed by the reference)
#define B_    8
#define CIN_  512
#define COUT_ 3
#define HW_   65536   // 256*256
#define ZDIM_ 512

// Final modulated+demodulated weights: [B][CIN][COUT]
__device__ float g_ww[B_ * CIN_ * COUT_];

// ---------------------------------------------------------------------------
// Kernel 1: style dense + modulate + demodulate. grid=(B), block=(512).
// One thread per input channel ci.
// ---------------------------------------------------------------------------
__global__ void style_kernel(const float* __restrict__ y,
                             const float* __restrict__ w,
                             const float* __restrict__ dense_w,
                             const float* __restrict__ dense_b) {
    const int b  = blockIdx.x;
    const int ci = threadIdx.x;          // 0..511

    __shared__ float ys[ZDIM_];
    ys[ci] = y[b * ZDIM_ + ci];
    __syncthreads();

    const float rc = 0.044194173824159216f;  // 1/sqrt(512) (both rc_conv and rc_dense)

    float acc = 0.0f;
#pragma unroll 8
    for (int z = 0; z < ZDIM_; ++z)
        acc = fmaf(ys[z], dense_w[z * CIN_ + ci], acc);

    const float s = acc * rc + dense_b[ci] + 1.0f;

    const float ww0 = rc * w[ci * COUT_ + 0] * s;
    const float ww1 = rc * w[ci * COUT_ + 1] * s;
    const float ww2 = rc * w[ci * COUT_ + 2] * s;

    // Block reduction of sum-of-squares per output channel
    __shared__ float red0[512], red1[512], red2[512];
    red0[ci] = ww0 * ww0;
    red1[ci] = ww1 * ww1;
    red2[ci] = ww2 * ww2;
    __syncthreads();
#pragma unroll
    for (int off = 256; off >= 1; off >>= 1) {
        if (ci < off) {
            red0[ci] += red0[ci + off];
            red1[ci] += red1[ci + off];
            red2[ci] += red2[ci + off];
        }
        __syncthreads();
    }

    const float d0 = rsqrtf(red0[0] + 1e-8f);
    const float d1 = rsqrtf(red1[0] + 1e-8f);
    const float d2 = rsqrtf(red2[0] + 1e-8f);

    float* o = g_ww + (b * CIN_ + ci) * COUT_;
    o[0] = ww0 * d0;
    o[1] = ww1 * d1;
    o[2] = ww2 * d2;
}

// ---------------------------------------------------------------------------
// Kernel 2: pointwise "conv" — streaming 537 MB of x, HBM-bound.
// grid=(HW/4/256, B), block=256. Each thread owns 4 consecutive pixels.
// ---------------------------------------------------------------------------
__global__ __launch_bounds__(256) void conv_kernel(const float* __restrict__ x,
                                                   float* __restrict__ out) {
    const int b    = blockIdx.y;
    const int pix4 = blockIdx.x * blockDim.x + threadIdx.x;  // 0 .. HW/4-1

    __shared__ float sw0[CIN_], sw1[CIN_], sw2[CIN_];
    for (int i = threadIdx.x; i < CIN_; i += blockDim.x) {
        const float* p = g_ww + (b * CIN_ + i) * COUT_;
        sw0[i] = p[0];
        sw1[i] = p[1];
        sw2[i] = p[2];
    }
    __syncthreads();

    const float4* xb = reinterpret_cast<const float4*>(
                           x + (size_t)b * CIN_ * HW_) + pix4;

    float4 a0 = make_float4(0.f, 0.f, 0.f, 0.f);
    float4 a1 = make_float4(0.f, 0.f, 0.f, 0.f);
    float4 a2 = make_float4(0.f, 0.f, 0.f, 0.f);

#pragma unroll 4
    for (int ci = 0; ci < CIN_; ++ci) {
        const float4 v  = xb[(size_t)ci * (HW_ / 4)];
        const float  w0 = sw0[ci];
        const float  w1 = sw1[ci];
        const float  w2 = sw2[ci];
        a0.x = fmaf(w0, v.x, a0.x); a0.y = fmaf(w0, v.y, a0.y);
        a0.z = fmaf(w0, v.z, a0.z); a0.w = fmaf(w0, v.w, a0.w);
        a1.x = fmaf(w1, v.x, a1.x); a1.y = fmaf(w1, v.y, a1.y);
        a1.z = fmaf(w1, v.z, a1.z); a1.w = fmaf(w1, v.w, a1.w);
        a2.x = fmaf(w2, v.x, a2.x); a2.y = fmaf(w2, v.y, a2.y);
        a2.z = fmaf(w2, v.z, a2.z); a2.w = fmaf(w2, v.w, a2.w);
    }

    float4* ob = reinterpret_cast<float4*>(out + (size_t)b * COUT_ * HW_);
    ob[0 * (HW_ / 4) + pix4] = a0;
    ob[1 * (HW_ / 4) + pix4] = a1;
    ob[2 * (HW_ / 4) + pix4] = a2;
}

// ---------------------------------------------------------------------------
// Inputs (metadata order): x, y, w, dense_w, dense_b. Output: float [8,3,256,256]
// ---------------------------------------------------------------------------
extern "C" void kernel_launch(void* const* d_in, const int* in_sizes, int n_in,
                              void* d_out, int out_size) {
    const float* x       = (const float*)d_in[0];
    const float* y       = (const float*)d_in[1];
    const float* w       = (const float*)d_in[2];
    const float* dense_w = (const float*)d_in[3];
    const float* dense_b = (const float*)d_in[4];
    float* out = (float*)d_out;

    style_kernel<<<B_, 512>>>(y, w, dense_w, dense_b);

    dim3 grid(HW_ / 4 / 256, B_);
    conv_kernel<<<grid, 256>>>(x, out);
}

// round 2
// speedup vs baseline: 1.1416x; 1.1416x over previous
#include <cuda_runtime.h>
#include <math.h>

#define B_    8
#define CIN_  512
#define COUT_ 3
#define HW_   65536   // 256*256
#define ZDIM_ 512

// Modulated (NOT yet demodulated) weights: [B][CIN][COUT]
__device__ float g_ww[B_ * CIN_ * COUT_];
// Partial sum-of-squares: [B][4 blocks][COUT]
__device__ float g_part[B_ * 4 * COUT_];

// ---------------------------------------------------------------------------
// Kernel 1: style dense + modulate + partial demod sums.
// grid=(B, 4), block=512 = 128 ci-lanes x 4 z-slices.
// ---------------------------------------------------------------------------
__global__ __launch_bounds__(512) void style_kernel(const float* __restrict__ y,
                                                    const float* __restrict__ w,
                                                    const float* __restrict__ dense_w,
                                                    const float* __restrict__ dense_b) {
    const int b    = blockIdx.x;
    const int gy   = blockIdx.y;            // ci group 0..3
    const int tid  = threadIdx.x;            // 0..511
    const int ci_l = tid & 127;
    const int zs   = tid >> 7;               // z-slice 0..3
    const int ci   = gy * 128 + ci_l;

    __shared__ float sy[ZDIM_];
    __shared__ float sp[512];
    __shared__ float swq[4][COUT_];

    sy[tid] = y[b * ZDIM_ + tid];
    __syncthreads();

    // partial dot over 128 z's
    float acc = 0.0f;
    const int z0 = zs * 128;
#pragma unroll 16
    for (int zz = 0; zz < 128; ++zz) {
        const int z = z0 + zz;
        acc = fmaf(sy[z], dense_w[(size_t)z * CIN_ + ci], acc);
    }
    sp[tid] = acc;
    __syncthreads();

    if (zs == 0) {
        const float rc = 0.044194173824159216f;   // 1/sqrt(512)
        const float dot = sp[ci_l] + sp[128 + ci_l] + sp[256 + ci_l] + sp[384 + ci_l];
        const float s = dot * rc + dense_b[ci] + 1.0f;

        const float ww0 = rc * w[ci * COUT_ + 0] * s;
        const float ww1 = rc * w[ci * COUT_ + 1] * s;
        const float ww2 = rc * w[ci * COUT_ + 2] * s;

        float* o = g_ww + (b * CIN_ + ci) * COUT_;
        o[0] = ww0; o[1] = ww1; o[2] = ww2;

        // warp-level reduce of squares (4 warps of the zs==0 group)
        float q0 = ww0 * ww0, q1 = ww1 * ww1, q2 = ww2 * ww2;
#pragma unroll
        for (int off = 16; off >= 1; off >>= 1) {
            q0 += __shfl_xor_sync(0xFFFFFFFF, q0, off);
            q1 += __shfl_xor_sync(0xFFFFFFFF, q1, off);
            q2 += __shfl_xor_sync(0xFFFFFFFF, q2, off);
        }
        const int warp = ci_l >> 5;
        if ((ci_l & 31) == 0) {
            swq[warp][0] = q0; swq[warp][1] = q1; swq[warp][2] = q2;
        }
    }
    __syncthreads();

    if (tid < COUT_) {
        g_part[(b * 4 + gy) * COUT_ + tid] =
            swq[0][tid] + swq[1][tid] + swq[2][tid] + swq[3][tid];
    }
}

// ---------------------------------------------------------------------------
// Kernel 2: pointwise conv, HBM streaming. grid=(128, B), block=128.
// Each thread owns one float4 of pixels, loops 512 channels.
// Demod factor d computed per-block from the 12 partial sums, applied at end.
// ---------------------------------------------------------------------------
__global__ __launch_bounds__(128) void conv_kernel(const float* __restrict__ x,
                                                   float* __restrict__ out) {
    const int b    = blockIdx.y;
    const int pix4 = blockIdx.x * 128 + threadIdx.x;  // 0 .. HW/4-1

    __shared__ float sw0[CIN_], sw1[CIN_], sw2[CIN_];
    __shared__ float sd[COUT_];

    if (threadIdx.x < COUT_) {
        const float* p = g_part + b * 4 * COUT_ + threadIdx.x;
        sd[threadIdx.x] = rsqrtf(p[0] + p[3] + p[6] + p[9] + 1e-8f);
    }
    for (int i = threadIdx.x; i < CIN_; i += 128) {
        const float* p = g_ww + (b * CIN_ + i) * COUT_;
        sw0[i] = p[0]; sw1[i] = p[1]; sw2[i] = p[2];
    }
    __syncthreads();

    const float4* xb = reinterpret_cast<const float4*>(
                           x + (size_t)b * CIN_ * HW_) + pix4;

    float4 a0 = make_float4(0.f, 0.f, 0.f, 0.f);
    float4 a1 = make_float4(0.f, 0.f, 0.f, 0.f);
    float4 a2 = make_float4(0.f, 0.f, 0.f, 0.f);

#pragma unroll 8
    for (int ci = 0; ci < CIN_; ++ci) {
        const float4 v  = xb[(size_t)ci * (HW_ / 4)];
        const float  w0 = sw0[ci];
        const float  w1 = sw1[ci];
        const float  w2 = sw2[ci];
        a0.x = fmaf(w0, v.x, a0.x); a0.y = fmaf(w0, v.y, a0.y);
        a0.z = fmaf(w0, v.z, a0.z); a0.w = fmaf(w0, v.w, a0.w);
        a1.x = fmaf(w1, v.x, a1.x); a1.y = fmaf(w1, v.y, a1.y);
        a1.z = fmaf(w1, v.z, a1.z); a1.w = fmaf(w1, v.w, a1.w);
        a2.x = fmaf(w2, v.x, a2.x); a2.y = fmaf(w2, v.y, a2.y);
        a2.z = fmaf(w2, v.z, a2.z); a2.w = fmaf(w2, v.w, a2.w);
    }

    const float d0 = sd[0], d1 = sd[1], d2 = sd[2];
    a0.x *= d0; a0.y *= d0; a0.z *= d0; a0.w *= d0;
    a1.x *= d1; a1.y *= d1; a1.z *= d1; a1.w *= d1;
    a2.x *= d2; a2.y *= d2; a2.z *= d2; a2.w *= d2;

    float4* ob = reinterpret_cast<float4*>(out + (size_t)b * COUT_ * HW_);
    ob[0 * (HW_ / 4) + pix4] = a0;
    ob[1 * (HW_ / 4) + pix4] = a1;
    ob[2 * (HW_ / 4) + pix4] = a2;
}

// ---------------------------------------------------------------------------
// Inputs: x, y, w, dense_w, dense_b. Output: float [8,3,256,256]
// ---------------------------------------------------------------------------
extern "C" void kernel_launch(void* const* d_in, const int* in_sizes, int n_in,
                              void* d_out, int out_size) {
    const float* x       = (const float*)d_in[0];
    const float* y       = (const float*)d_in[1];
    const float* w       = (const float*)d_in[2];
    const float* dense_w = (const float*)d_in[3];
    const float* dense_b = (const float*)d_in[4];
    float* out = (float*)d_out;

    dim3 sgrid(B_, 4);
    style_kernel<<<sgrid, 512>>>(y, w, dense_w, dense_b);

    dim3 cgrid(HW_ / 4 / 128, B_);
    conv_kernel<<<cgrid, 128>>>(x, out);
}